// round 14
// baseline (speedup 1.0000x reference)
#include <cuda_runtime.h>
#include <cuda_bf16.h>
#include <cuda_fp16.h>

// ---------------------------------------------------------------------------
//   N=8192, DIN=768; layer1 dh=64 (P cols 65 -> pad 72), layer2 dh=32 (pad 40)
// Per GAT layer the softmax source-term cancels:
//   Z_i = (sum_j A_ij w_j H_j) / (sum_j A_ij w_j),  w_j = exp(H_j . a_dst)
// => one GEMM  S = A_bits @ [w*H | w]  per layer, single fp16 P, fp32 acc.
// P k-words PERMUTED within 8-word groups (p<4 -> 2p, else 2p-7) -> LDS.64.
// packh1: blocks 0-127 H1=X@W1, blocks 128-2175 pack A (wave-1 overlap).
// THIS ROUND (vs R10 best): ONLY k_fin2 parallelism 64 -> 256 blocks
// (2048 warp-slots) + k_head sums 2048 partials.
// ---------------------------------------------------------------------------

#define NN 8192
#define KSPLIT 4

// -------- device scratch (static, no allocations) --------
__device__ uint4     g_Abits4[NN * 64];              // 8192 x 8192 bits, 8 MB
__device__ float     g_H1[NN * 64];                  // X @ W1
__device__ unsigned  g_Pt1[72 * (NN / 2)];           // P1 fp16 [72][8192] col-major (k-permuted)
__device__ unsigned  g_Pt2[40 * (NN / 2)];           // P2 fp16 (k-permuted)
__device__ float     g_S1p[KSPLIT * NN * 72];        // k-split partials, layer 1
__device__ float     g_S2p[KSPLIT * NN * 40];        // k-split partials, layer 2
__device__ float     g_gpart[2048 * 64];             // per-warp-slot sums for the mean

__device__ __forceinline__ float eluf(float x) { return x > 0.f ? x : expm1f(x); }

__device__ __forceinline__ int permute8(int u) {     // within 8-word group
    int p = u & 7;
    return (u & ~7) | ((p < 4) ? (2 * p) : (2 * p - 7));
}

__device__ __forceinline__ void cp_async16(void* dst, const void* src) {
    unsigned d = (unsigned)__cvta_generic_to_shared(dst);
    asm volatile("cp.async.cg.shared.global [%0], [%1], 16;\n" :: "r"(d), "l"(src));
}
__device__ __forceinline__ void cp_commit() {
    asm volatile("cp.async.commit_group;\n");
}
__device__ __forceinline__ void cp_wait1() {
    asm volatile("cp.async.wait_group 1;\n");
}

// -------- FUSED: blocks 0-127 compute H1 = X@W1; blocks 128-2175 pack A -----
__global__ void __launch_bounds__(256) k_packh1(const int* __restrict__ A,
                                                const float* __restrict__ X,
                                                const float* __restrict__ W) {
    __shared__ float Xs[64][33];
    __shared__ float Ws[32][64];
    int tid = threadIdx.x;

    if (blockIdx.x < 128) {
        int rb = blockIdx.x * 64;
        int tx = tid & 15;
        int ty = tid >> 4;
        float acc[4][4];
#pragma unroll
        for (int i = 0; i < 4; i++)
#pragma unroll
            for (int j = 0; j < 4; j++) acc[i][j] = 0.f;

        for (int k0 = 0; k0 < 768; k0 += 32) {
            {
                int r = tid >> 3;
                int c4 = (tid & 7) * 4;
#pragma unroll
                for (int i = 0; i < 2; i++) {
                    float4 v = *reinterpret_cast<const float4*>(
                        &X[(long long)(rb + r + i * 32) * 768 + k0 + c4]);
                    Xs[r + i * 32][c4 + 0] = v.x; Xs[r + i * 32][c4 + 1] = v.y;
                    Xs[r + i * 32][c4 + 2] = v.z; Xs[r + i * 32][c4 + 3] = v.w;
                }
#pragma unroll
                for (int i = 0; i < 2; i++) {
                    int kk = (tid >> 4) + i * 16;
                    float4 v = *reinterpret_cast<const float4*>(
                        &W[(long long)(k0 + kk) * 64 + (tid & 15) * 4]);
                    Ws[kk][(tid & 15) * 4 + 0] = v.x; Ws[kk][(tid & 15) * 4 + 1] = v.y;
                    Ws[kk][(tid & 15) * 4 + 2] = v.z; Ws[kk][(tid & 15) * 4 + 3] = v.w;
                }
            }
            __syncthreads();
#pragma unroll
            for (int kk = 0; kk < 32; kk++) {
                float b0 = Ws[kk][tx * 4 + 0], b1 = Ws[kk][tx * 4 + 1];
                float b2 = Ws[kk][tx * 4 + 2], b3 = Ws[kk][tx * 4 + 3];
#pragma unroll
                for (int i = 0; i < 4; i++) {
                    float a = Xs[ty * 4 + i][kk];
                    acc[i][0] = fmaf(a, b0, acc[i][0]);
                    acc[i][1] = fmaf(a, b1, acc[i][1]);
                    acc[i][2] = fmaf(a, b2, acc[i][2]);
                    acc[i][3] = fmaf(a, b3, acc[i][3]);
                }
            }
            __syncthreads();
        }
#pragma unroll
        for (int i = 0; i < 4; i++)
#pragma unroll
            for (int j = 0; j < 4; j++)
                g_H1[(long long)(rb + ty * 4 + i) * 64 + tx * 4 + j] = acc[i][j];
    } else {
        unsigned* bits = reinterpret_cast<unsigned*>(g_Abits4);
        int bid = blockIdx.x - 128;
        int warp = (bid * 256 + tid) >> 5;
        int lane = tid & 31;
        const int nwarps = (2048 * 256) >> 5;
        const int ngroups = (NN * (NN / 32)) / 8;
        for (int g = warp; g < ngroups; g += nwarps) {
            long long base = (long long)g * 256 + lane;
            int v[8];
#pragma unroll
            for (int i = 0; i < 8; i++) v[i] = A[base + i * 32];
#pragma unroll
            for (int i = 0; i < 8; i++) {
                unsigned m = __ballot_sync(0xFFFFFFFFu, v[i] != 0);
                if (lane == 0) bits[g * 8 + i] = m;
            }
        }
    }
}

// -------- build P1 = [w*H1 | w] fp16, k-permuted, coalesced, pads zeroed ----
__global__ void k_buildP1(const float* __restrict__ a1) {
    __shared__ float pst[65][66];
    int tid = threadIdx.x, lane = tid & 31, warp = tid >> 5;
    int base = blockIdx.x * 64;
    float ad0 = a1[64 + lane], ad1 = a1[96 + lane];
#pragma unroll
    for (int i = 0; i < 8; i++) {
        int n = base + warp * 8 + i;
        float h0 = g_H1[(long long)n * 64 + lane];
        float h1 = g_H1[(long long)n * 64 + 32 + lane];
        float p = h0 * ad0 + h1 * ad1;
#pragma unroll
        for (int o = 16; o; o >>= 1) p += __shfl_xor_sync(0xFFFFFFFFu, p, o);
        float w = expf(p);
        int jl = warp * 8 + i;
        pst[lane][jl] = w * h0;
        pst[32 + lane][jl] = w * h1;
        if (lane == 0) pst[64][jl] = w;
    }
    __syncthreads();
    for (int idx = tid; idx < 72 * 32; idx += 256) {
        int col = idx >> 5, u = idx & 31;
        float f0 = (col < 65) ? pst[col][2 * u] : 0.f;
        float f1 = (col < 65) ? pst[col][2 * u + 1] : 0.f;
        unsigned hw = (unsigned)__half_as_ushort(__float2half_rn(f0)) |
                      ((unsigned)__half_as_ushort(__float2half_rn(f1)) << 16);
        g_Pt1[col * (NN / 2) + blockIdx.x * 32 + permute8(u)] = hw;
    }
}

// -------- fp16 mma helper --------
__device__ __forceinline__ void mma16816_f16(float (&d)[4], unsigned a0, unsigned a1,
                                             unsigned a2, unsigned a3, unsigned b0, unsigned b1) {
    asm volatile(
        "mma.sync.aligned.m16n8k16.row.col.f32.f16.f16.f32 "
        "{%0,%1,%2,%3}, {%4,%5,%6,%7}, {%8,%9}, {%0,%1,%2,%3};\n"
        : "+f"(d[0]), "+f"(d[1]), "+f"(d[2]), "+f"(d[3])
        : "r"(a0), "r"(a1), "r"(a2), "r"(a3), "r"(b0), "r"(b1));
}

// -------- S = A_bits @ P : m=32/warp, cp.async double buffer, fp16 ----------
// grid (32 m-tiles of 256 rows, 4 k-splits), 256 threads.
template <int LAYER>
__global__ void __launch_bounds__(256, 2) k_attn() {
    constexpr int NT = (LAYER == 1) ? 9 : 5;
    constexpr int CPAD = NT * 8;
    constexpr int TW = CPAD * 72;                 // u32 per stage
    const unsigned* __restrict__ Pt = (LAYER == 1) ? g_Pt1 : g_Pt2;
    float* __restrict__ Sp = (LAYER == 1) ? g_S1p : g_S2p;

    extern __shared__ unsigned sB[];              // [stage][TW]

    int tid = threadIdx.x, lane = tid & 31, warp = tid >> 5;
    int g = lane >> 2, c = lane & 3;
    int R = blockIdx.x * 256 + warp * 32;

    float acc0[NT][4], acc1[NT][4];
#pragma unroll
    for (int t = 0; t < NT; t++)
#pragma unroll
        for (int i = 0; i < 4; i++) { acc0[t][i] = 0.f; acc1[t][i] = 0.f; }

    const int ch0 = blockIdx.y * 16;              // 16 chunks of k=128 per split

    auto pk = [](unsigned t) -> unsigned {        // 2 bits -> fp16x2 of {0,1}
        return ((t & 1u) | ((t << 15) & 0x10000u)) * 0x3C00u;
    };
    auto issue_stage = [&](int st, int ch) {
        int koff = ch * 64;                        // u32 offset along k
        unsigned* dsh = sB + st * TW;
        for (int i = tid; i < CPAD * 16; i += 256) {
            int n = i >> 4, kc = (i & 15) * 4;
            cp_async16(&dsh[n * 72 + kc], &Pt[n * (NN / 2) + koff + kc]);
        }
    };

    issue_stage(0, ch0);
    cp_commit();
    uint4 nb0 = g_Abits4[(long long)(R + g) * 64 + ch0];
    uint4 nb1 = g_Abits4[(long long)(R + 8 + g) * 64 + ch0];
    uint4 nb2 = g_Abits4[(long long)(R + 16 + g) * 64 + ch0];
    uint4 nb3 = g_Abits4[(long long)(R + 24 + g) * 64 + ch0];

    for (int kk = 0; kk < 16; kk++) {
        uint4 b0 = nb0, b1 = nb1, b2 = nb2, b3 = nb3;
        if (kk + 1 < 16) issue_stage((kk + 1) & 1, ch0 + kk + 1);
        cp_commit();
        if (kk + 1 < 16) {
            int ch = ch0 + kk + 1;
            nb0 = g_Abits4[(long long)(R + g) * 64 + ch];
            nb1 = g_Abits4[(long long)(R + 8 + g) * 64 + ch];
            nb2 = g_Abits4[(long long)(R + 16 + g) * 64 + ch];
            nb3 = g_Abits4[(long long)(R + 24 + g) * 64 + ch];
        }
        cp_wait1();
        __syncthreads();

        const unsigned* bh = sB + (kk & 1) * TW;
        unsigned w0[4] = {b0.x, b0.y, b0.z, b0.w};
        unsigned w1[4] = {b1.x, b1.y, b1.z, b1.w};
        unsigned w2[4] = {b2.x, b2.y, b2.z, b2.w};
        unsigned w3[4] = {b3.x, b3.y, b3.z, b3.w};
#pragma unroll
        for (int s = 0; s < 8; s++) {
            int sh = (s & 1) * 16 + 2 * c;
            unsigned t0 = w0[s >> 1] >> sh;
            unsigned t1 = w1[s >> 1] >> sh;
            unsigned t2 = w2[s >> 1] >> sh;
            unsigned t3 = w3[s >> 1] >> sh;
            unsigned a0 = pk(t0), a1r = pk(t1);
            unsigned a2 = pk(t0 >> 8), a3 = pk(t1 >> 8);
            unsigned e0 = pk(t2), e1 = pk(t3);
            unsigned e2 = pk(t2 >> 8), e3 = pk(t3 >> 8);
#pragma unroll
            for (int t = 0; t < NT; t++) {
                int bi = (t * 8 + g) * 72 + s * 8 + 2 * c;
                uint2 bb = *reinterpret_cast<const uint2*>(&bh[bi]);
                mma16816_f16(acc0[t], a0, a1r, a2, a3, bb.x, bb.y);
                mma16816_f16(acc1[t], e0, e1, e2, e3, bb.x, bb.y);
            }
        }
        __syncthreads();
    }

    float* so = Sp + ((long long)blockIdx.y * NN + R + g) * CPAD;
#pragma unroll
    for (int t = 0; t < NT; t++) {
        int col = t * 8 + 2 * c;
        so[col] = acc0[t][0];
        so[col + 1] = acc0[t][1];
        so[8 * CPAD + col] = acc0[t][2];
        so[8 * CPAD + col + 1] = acc0[t][3];
        so[16 * CPAD + col] = acc1[t][0];
        so[16 * CPAD + col + 1] = acc1[t][1];
        so[24 * CPAD + col] = acc1[t][2];
        so[24 * CPAD + col + 1] = acc1[t][3];
    }
}

// -------- finalize layer1 -> P2 (fp16, k-permuted), 16 rows/block, 512 blks -
__global__ void k_fin1(const float* __restrict__ W21, const float* __restrict__ b21,
                       const float* __restrict__ Wg2, const float* __restrict__ a2) {
    __shared__ float W21s[64 * 64], Wg2s[64 * 32], b21s[64], a2ds[32];
    __shared__ float zrow[8][64], orow[8][64];
    __shared__ float pst[33][18];
    int tid = threadIdx.x, lane = tid & 31, warp = tid >> 5;
    int base = blockIdx.x * 16;
    for (int i = tid; i < 4096; i += 256) W21s[i] = W21[i];
    for (int i = tid; i < 2048; i += 256) Wg2s[i] = Wg2[i];
    if (tid < 64) b21s[tid] = b21[tid];
    if (tid < 32) a2ds[tid] = a2[32 + tid];
    __syncthreads();

#pragma unroll
    for (int i = 0; i < 2; i++) {
        int row = base + warp * 2 + i;
        float s0 = 0.f, s1 = 0.f, sd = 0.f;
#pragma unroll
        for (int k = 0; k < KSPLIT; k++) {
            const float* sp = g_S1p + ((long long)k * NN + row) * 72;
            s0 += sp[lane]; s1 += sp[lane + 32]; sd += sp[64];
        }
        float inv = 1.f / sd;
        zrow[warp][lane] = s0 * inv;
        zrow[warp][lane + 32] = s1 * inv;
        __syncwarp();
        float oa = b21s[lane], ob = b21s[lane + 32];
#pragma unroll
        for (int cc = 0; cc < 64; cc++) {
            float z = zrow[warp][cc];
            oa = fmaf(z, W21s[cc * 64 + lane], oa);
            ob = fmaf(z, W21s[cc * 64 + lane + 32], ob);
        }
        oa = eluf(oa); ob = eluf(ob);
        orow[warp][lane] = oa;
        orow[warp][lane + 32] = ob;
        __syncwarp();
        float h = 0.f;
#pragma unroll
        for (int cc = 0; cc < 64; cc++) h = fmaf(orow[warp][cc], Wg2s[cc * 32 + lane], h);
        float p = h * a2ds[lane];
#pragma unroll
        for (int o = 16; o; o >>= 1) p += __shfl_xor_sync(0xFFFFFFFFu, p, o);
        float w2 = expf(p);
        int jl = warp * 2 + i;
        pst[lane][jl] = w2 * h;
        if (lane == 0) pst[32][jl] = w2;
        __syncwarp();
    }
    __syncthreads();
    for (int idx = tid; idx < 40 * 8; idx += 256) {
        int col = idx >> 3, u = idx & 7;
        float f0 = (col < 33) ? pst[col][2 * u] : 0.f;
        float f1 = (col < 33) ? pst[col][2 * u + 1] : 0.f;
        unsigned hw = (unsigned)__half_as_ushort(__float2half_rn(f0)) |
                      ((unsigned)__half_as_ushort(__float2half_rn(f1)) << 16);
        g_Pt2[col * (NN / 2) + blockIdx.x * 8 + permute8(u)] = hw;
    }
}

// -------- finalize layer2: o2 = elu(Z2@W22+b22), 256 blocks, 4 rows/slot ----
__global__ void k_fin2(const float* __restrict__ W22, const float* __restrict__ b22) {
    __shared__ float W22s[32 * 64], b22s[64];
    __shared__ float zr[8][32];
    int tid = threadIdx.x, lane = tid & 31, warp = tid >> 5;
    for (int i = tid; i < 2048; i += 256) W22s[i] = W22[i];
    if (tid < 64) b22s[tid] = b22[tid];
    __syncthreads();
    int wgl = blockIdx.x * 8 + warp;     // 0..2047
    float aa = 0.f, ab = 0.f;
    for (int row = wgl; row < NN; row += 2048) {
        float s = 0.f, sdp = 0.f;
#pragma unroll
        for (int k = 0; k < KSPLIT; k++) {
            const float* sp = g_S2p + ((long long)k * NN + row) * 40;
            s += sp[lane]; sdp += sp[32];
        }
        zr[warp][lane] = s / sdp;
        __syncwarp();
        float oa = b22s[lane], ob = b22s[lane + 32];
#pragma unroll
        for (int cc = 0; cc < 32; cc++) {
            float z = zr[warp][cc];
            oa = fmaf(z, W22s[cc * 64 + lane], oa);
            ob = fmaf(z, W22s[cc * 64 + lane + 32], ob);
        }
        aa += eluf(oa); ab += eluf(ob);
        __syncwarp();
    }
    g_gpart[(long long)wgl * 64 + lane] = aa;
    g_gpart[(long long)wgl * 64 + lane + 32] = ab;
}

// -------- head: mean -> relu dense -> dense(2) --------
__global__ void k_head(const float* __restrict__ M1, const float* __restrict__ bm1,
                       const float* __restrict__ M2, const float* __restrict__ bm2,
                       float* __restrict__ out) {
    __shared__ float gs[64], hs[64];
    int t = threadIdx.x;
    float s_[4] = {0.f, 0.f, 0.f, 0.f};
    for (int w = 0; w < 2048; w += 4) {
#pragma unroll
        for (int p = 0; p < 4; p++) s_[p] += g_gpart[(w + p) * 64 + t];
    }
    gs[t] = ((s_[0] + s_[1]) + (s_[2] + s_[3])) * (1.f / 8192.f);
    __syncthreads();
    float h = bm1[t];
    for (int cc = 0; cc < 64; cc++) h = fmaf(gs[cc], M1[cc * 64 + t], h);
    hs[t] = fmaxf(h, 0.f);
    __syncthreads();
    if (t < 2) {
        float o = bm2[t];
        for (int cc = 0; cc < 64; cc++) o = fmaf(hs[cc], M2[cc * 2 + t], o);
        out[t] = o;
    }
}

extern "C" void kernel_launch(void* const* d_in, const int* in_sizes, int n_in,
                              void* d_out, int out_size) {
    const float* X   = (const float*)d_in[0];
    const int*   A   = (const int*)d_in[1];
    const float* W1  = (const float*)d_in[2];
    const float* a1  = (const float*)d_in[3];
    const float* W21 = (const float*)d_in[4];
    const float* b21 = (const float*)d_in[5];
    const float* Wg2 = (const float*)d_in[6];
    const float* a2  = (const float*)d_in[7];
    const float* W22 = (const float*)d_in[8];
    const float* b22 = (const float*)d_in[9];
    const float* M1  = (const float*)d_in[10];
    const float* bm1 = (const float*)d_in[11];
    const float* M2  = (const float*)d_in[12];
    const float* bm2 = (const float*)d_in[13];
    float* out = (float*)d_out;

    const int smem1 = 2 * 72 * 72 * (int)sizeof(unsigned);   // 41472 B
    const int smem2 = 2 * 40 * 72 * (int)sizeof(unsigned);   // 23040 B
    static bool attr_done = false;
    if (!attr_done) {
        cudaFuncSetAttribute(k_attn<1>, cudaFuncAttributeMaxDynamicSharedMemorySize, smem1);
        cudaFuncSetAttribute(k_attn<2>, cudaFuncAttributeMaxDynamicSharedMemorySize, smem2);
        attr_done = true;
    }

    k_packh1<<<2176, 256>>>(A, X, W1);     // h1 blocks first, pack overlapped
    k_buildP1<<<128, 256>>>(a1);
    k_attn<1><<<dim3(32, KSPLIT), 256, smem1>>>();
    k_fin1<<<512, 256>>>(W21, b21, Wg2, a2);
    k_attn<2><<<dim3(32, KSPLIT), 256, smem2>>>();
    k_fin2<<<256, 256>>>(W22, b22);
    k_head<<<1, 64>>>(M1, bm1, M2, bm2, out);
}

// round 15
// speedup vs baseline: 1.0874x; 1.0874x over previous
#include <cuda_runtime.h>
#include <cuda_bf16.h>
#include <cuda_fp16.h>

// ---------------------------------------------------------------------------
//   N=8192, DIN=768; layer1 dh=64 (P cols 65 -> pad 72), layer2 dh=32 (pad 40)
// Per GAT layer the softmax source-term cancels:
//   Z_i = (sum_j A_ij w_j H_j) / (sum_j A_ij w_j),  w_j = exp(H_j . a_dst)
// => one GEMM  S = A_bits @ [w*H | w]  per layer, single fp16 P, fp32 acc.
// P k-words PERMUTED within 8-word groups (p<4 -> 2p, else 2p-7) -> LDS.64.
// packh1: blocks 0-127 H1=X@W1, blocks 128-2175 pack A (wave-1 overlap).
// THIS ROUND (vs R10 best): ONLY k_head parallelized (256 threads,
// 4-group strided partial sums + deterministic smem reduce).
// ---------------------------------------------------------------------------

#define NN 8192
#define KSPLIT 4

// -------- device scratch (static, no allocations) --------
__device__ uint4     g_Abits4[NN * 64];              // 8192 x 8192 bits, 8 MB
__device__ float     g_H1[NN * 64];                  // X @ W1
__device__ unsigned  g_Pt1[72 * (NN / 2)];           // P1 fp16 [72][8192] col-major (k-permuted)
__device__ unsigned  g_Pt2[40 * (NN / 2)];           // P2 fp16 (k-permuted)
__device__ float     g_S1p[KSPLIT * NN * 72];        // k-split partials, layer 1
__device__ float     g_S2p[KSPLIT * NN * 40];        // k-split partials, layer 2
__device__ float     g_gpart[512 * 64];              // per-warp sums for the mean

__device__ __forceinline__ float eluf(float x) { return x > 0.f ? x : expm1f(x); }

__device__ __forceinline__ int permute8(int u) {     // within 8-word group
    int p = u & 7;
    return (u & ~7) | ((p < 4) ? (2 * p) : (2 * p - 7));
}

__device__ __forceinline__ void cp_async16(void* dst, const void* src) {
    unsigned d = (unsigned)__cvta_generic_to_shared(dst);
    asm volatile("cp.async.cg.shared.global [%0], [%1], 16;\n" :: "r"(d), "l"(src));
}
__device__ __forceinline__ void cp_commit() {
    asm volatile("cp.async.commit_group;\n");
}
__device__ __forceinline__ void cp_wait1() {
    asm volatile("cp.async.wait_group 1;\n");
}

// -------- FUSED: blocks 0-127 compute H1 = X@W1; blocks 128-2175 pack A -----
__global__ void __launch_bounds__(256) k_packh1(const int* __restrict__ A,
                                                const float* __restrict__ X,
                                                const float* __restrict__ W) {
    __shared__ float Xs[64][33];
    __shared__ float Ws[32][64];
    int tid = threadIdx.x;

    if (blockIdx.x < 128) {
        int rb = blockIdx.x * 64;
        int tx = tid & 15;
        int ty = tid >> 4;
        float acc[4][4];
#pragma unroll
        for (int i = 0; i < 4; i++)
#pragma unroll
            for (int j = 0; j < 4; j++) acc[i][j] = 0.f;

        for (int k0 = 0; k0 < 768; k0 += 32) {
            {
                int r = tid >> 3;
                int c4 = (tid & 7) * 4;
#pragma unroll
                for (int i = 0; i < 2; i++) {
                    float4 v = *reinterpret_cast<const float4*>(
                        &X[(long long)(rb + r + i * 32) * 768 + k0 + c4]);
                    Xs[r + i * 32][c4 + 0] = v.x; Xs[r + i * 32][c4 + 1] = v.y;
                    Xs[r + i * 32][c4 + 2] = v.z; Xs[r + i * 32][c4 + 3] = v.w;
                }
#pragma unroll
                for (int i = 0; i < 2; i++) {
                    int kk = (tid >> 4) + i * 16;
                    float4 v = *reinterpret_cast<const float4*>(
                        &W[(long long)(k0 + kk) * 64 + (tid & 15) * 4]);
                    Ws[kk][(tid & 15) * 4 + 0] = v.x; Ws[kk][(tid & 15) * 4 + 1] = v.y;
                    Ws[kk][(tid & 15) * 4 + 2] = v.z; Ws[kk][(tid & 15) * 4 + 3] = v.w;
                }
            }
            __syncthreads();
#pragma unroll
            for (int kk = 0; kk < 32; kk++) {
                float b0 = Ws[kk][tx * 4 + 0], b1 = Ws[kk][tx * 4 + 1];
                float b2 = Ws[kk][tx * 4 + 2], b3 = Ws[kk][tx * 4 + 3];
#pragma unroll
                for (int i = 0; i < 4; i++) {
                    float a = Xs[ty * 4 + i][kk];
                    acc[i][0] = fmaf(a, b0, acc[i][0]);
                    acc[i][1] = fmaf(a, b1, acc[i][1]);
                    acc[i][2] = fmaf(a, b2, acc[i][2]);
                    acc[i][3] = fmaf(a, b3, acc[i][3]);
                }
            }
            __syncthreads();
        }
#pragma unroll
        for (int i = 0; i < 4; i++)
#pragma unroll
            for (int j = 0; j < 4; j++)
                g_H1[(long long)(rb + ty * 4 + i) * 64 + tx * 4 + j] = acc[i][j];
    } else {
        unsigned* bits = reinterpret_cast<unsigned*>(g_Abits4);
        int bid = blockIdx.x - 128;
        int warp = (bid * 256 + tid) >> 5;
        int lane = tid & 31;
        const int nwarps = (2048 * 256) >> 5;
        const int ngroups = (NN * (NN / 32)) / 8;
        for (int g = warp; g < ngroups; g += nwarps) {
            long long base = (long long)g * 256 + lane;
            int v[8];
#pragma unroll
            for (int i = 0; i < 8; i++) v[i] = A[base + i * 32];
#pragma unroll
            for (int i = 0; i < 8; i++) {
                unsigned m = __ballot_sync(0xFFFFFFFFu, v[i] != 0);
                if (lane == 0) bits[g * 8 + i] = m;
            }
        }
    }
}

// -------- build P1 = [w*H1 | w] fp16, k-permuted, coalesced, pads zeroed ----
__global__ void k_buildP1(const float* __restrict__ a1) {
    __shared__ float pst[65][66];
    int tid = threadIdx.x, lane = tid & 31, warp = tid >> 5;
    int base = blockIdx.x * 64;
    float ad0 = a1[64 + lane], ad1 = a1[96 + lane];
#pragma unroll
    for (int i = 0; i < 8; i++) {
        int n = base + warp * 8 + i;
        float h0 = g_H1[(long long)n * 64 + lane];
        float h1 = g_H1[(long long)n * 64 + 32 + lane];
        float p = h0 * ad0 + h1 * ad1;
#pragma unroll
        for (int o = 16; o; o >>= 1) p += __shfl_xor_sync(0xFFFFFFFFu, p, o);
        float w = expf(p);
        int jl = warp * 8 + i;
        pst[lane][jl] = w * h0;
        pst[32 + lane][jl] = w * h1;
        if (lane == 0) pst[64][jl] = w;
    }
    __syncthreads();
    for (int idx = tid; idx < 72 * 32; idx += 256) {
        int col = idx >> 5, u = idx & 31;
        float f0 = (col < 65) ? pst[col][2 * u] : 0.f;
        float f1 = (col < 65) ? pst[col][2 * u + 1] : 0.f;
        unsigned hw = (unsigned)__half_as_ushort(__float2half_rn(f0)) |
                      ((unsigned)__half_as_ushort(__float2half_rn(f1)) << 16);
        g_Pt1[col * (NN / 2) + blockIdx.x * 32 + permute8(u)] = hw;
    }
}

// -------- fp16 mma helper --------
__device__ __forceinline__ void mma16816_f16(float (&d)[4], unsigned a0, unsigned a1,
                                             unsigned a2, unsigned a3, unsigned b0, unsigned b1) {
    asm volatile(
        "mma.sync.aligned.m16n8k16.row.col.f32.f16.f16.f32 "
        "{%0,%1,%2,%3}, {%4,%5,%6,%7}, {%8,%9}, {%0,%1,%2,%3};\n"
        : "+f"(d[0]), "+f"(d[1]), "+f"(d[2]), "+f"(d[3])
        : "r"(a0), "r"(a1), "r"(a2), "r"(a3), "r"(b0), "r"(b1));
}

// -------- S = A_bits @ P : m=32/warp, cp.async double buffer, fp16 ----------
// grid (32 m-tiles of 256 rows, 4 k-splits), 256 threads.
template <int LAYER>
__global__ void __launch_bounds__(256, 2) k_attn() {
    constexpr int NT = (LAYER == 1) ? 9 : 5;
    constexpr int CPAD = NT * 8;
    constexpr int TW = CPAD * 72;                 // u32 per stage
    const unsigned* __restrict__ Pt = (LAYER == 1) ? g_Pt1 : g_Pt2;
    float* __restrict__ Sp = (LAYER == 1) ? g_S1p : g_S2p;

    extern __shared__ unsigned sB[];              // [stage][TW]

    int tid = threadIdx.x, lane = tid & 31, warp = tid >> 5;
    int g = lane >> 2, c = lane & 3;
    int R = blockIdx.x * 256 + warp * 32;

    float acc0[NT][4], acc1[NT][4];
#pragma unroll
    for (int t = 0; t < NT; t++)
#pragma unroll
        for (int i = 0; i < 4; i++) { acc0[t][i] = 0.f; acc1[t][i] = 0.f; }

    const int ch0 = blockIdx.y * 16;              // 16 chunks of k=128 per split

    auto pk = [](unsigned t) -> unsigned {        // 2 bits -> fp16x2 of {0,1}
        return ((t & 1u) | ((t << 15) & 0x10000u)) * 0x3C00u;
    };
    auto issue_stage = [&](int st, int ch) {
        int koff = ch * 64;                        // u32 offset along k
        unsigned* dsh = sB + st * TW;
        for (int i = tid; i < CPAD * 16; i += 256) {
            int n = i >> 4, kc = (i & 15) * 4;
            cp_async16(&dsh[n * 72 + kc], &Pt[n * (NN / 2) + koff + kc]);
        }
    };

    issue_stage(0, ch0);
    cp_commit();
    uint4 nb0 = g_Abits4[(long long)(R + g) * 64 + ch0];
    uint4 nb1 = g_Abits4[(long long)(R + 8 + g) * 64 + ch0];
    uint4 nb2 = g_Abits4[(long long)(R + 16 + g) * 64 + ch0];
    uint4 nb3 = g_Abits4[(long long)(R + 24 + g) * 64 + ch0];

    for (int kk = 0; kk < 16; kk++) {
        uint4 b0 = nb0, b1 = nb1, b2 = nb2, b3 = nb3;
        if (kk + 1 < 16) issue_stage((kk + 1) & 1, ch0 + kk + 1);
        cp_commit();
        if (kk + 1 < 16) {
            int ch = ch0 + kk + 1;
            nb0 = g_Abits4[(long long)(R + g) * 64 + ch];
            nb1 = g_Abits4[(long long)(R + 8 + g) * 64 + ch];
            nb2 = g_Abits4[(long long)(R + 16 + g) * 64 + ch];
            nb3 = g_Abits4[(long long)(R + 24 + g) * 64 + ch];
        }
        cp_wait1();
        __syncthreads();

        const unsigned* bh = sB + (kk & 1) * TW;
        unsigned w0[4] = {b0.x, b0.y, b0.z, b0.w};
        unsigned w1[4] = {b1.x, b1.y, b1.z, b1.w};
        unsigned w2[4] = {b2.x, b2.y, b2.z, b2.w};
        unsigned w3[4] = {b3.x, b3.y, b3.z, b3.w};
#pragma unroll
        for (int s = 0; s < 8; s++) {
            int sh = (s & 1) * 16 + 2 * c;
            unsigned t0 = w0[s >> 1] >> sh;
            unsigned t1 = w1[s >> 1] >> sh;
            unsigned t2 = w2[s >> 1] >> sh;
            unsigned t3 = w3[s >> 1] >> sh;
            unsigned a0 = pk(t0), a1r = pk(t1);
            unsigned a2 = pk(t0 >> 8), a3 = pk(t1 >> 8);
            unsigned e0 = pk(t2), e1 = pk(t3);
            unsigned e2 = pk(t2 >> 8), e3 = pk(t3 >> 8);
#pragma unroll
            for (int t = 0; t < NT; t++) {
                int bi = (t * 8 + g) * 72 + s * 8 + 2 * c;
                uint2 bb = *reinterpret_cast<const uint2*>(&bh[bi]);
                mma16816_f16(acc0[t], a0, a1r, a2, a3, bb.x, bb.y);
                mma16816_f16(acc1[t], e0, e1, e2, e3, bb.x, bb.y);
            }
        }
        __syncthreads();
    }

    float* so = Sp + ((long long)blockIdx.y * NN + R + g) * CPAD;
#pragma unroll
    for (int t = 0; t < NT; t++) {
        int col = t * 8 + 2 * c;
        so[col] = acc0[t][0];
        so[col + 1] = acc0[t][1];
        so[8 * CPAD + col] = acc0[t][2];
        so[8 * CPAD + col + 1] = acc0[t][3];
        so[16 * CPAD + col] = acc1[t][0];
        so[16 * CPAD + col + 1] = acc1[t][1];
        so[24 * CPAD + col] = acc1[t][2];
        so[24 * CPAD + col + 1] = acc1[t][3];
    }
}

// -------- finalize layer1 -> P2 (fp16, k-permuted), 16 rows/block, 512 blks -
__global__ void k_fin1(const float* __restrict__ W21, const float* __restrict__ b21,
                       const float* __restrict__ Wg2, const float* __restrict__ a2) {
    __shared__ float W21s[64 * 64], Wg2s[64 * 32], b21s[64], a2ds[32];
    __shared__ float zrow[8][64], orow[8][64];
    __shared__ float pst[33][18];
    int tid = threadIdx.x, lane = tid & 31, warp = tid >> 5;
    int base = blockIdx.x * 16;
    for (int i = tid; i < 4096; i += 256) W21s[i] = W21[i];
    for (int i = tid; i < 2048; i += 256) Wg2s[i] = Wg2[i];
    if (tid < 64) b21s[tid] = b21[tid];
    if (tid < 32) a2ds[tid] = a2[32 + tid];
    __syncthreads();

#pragma unroll
    for (int i = 0; i < 2; i++) {
        int row = base + warp * 2 + i;
        float s0 = 0.f, s1 = 0.f, sd = 0.f;
#pragma unroll
        for (int k = 0; k < KSPLIT; k++) {
            const float* sp = g_S1p + ((long long)k * NN + row) * 72;
            s0 += sp[lane]; s1 += sp[lane + 32]; sd += sp[64];
        }
        float inv = 1.f / sd;
        zrow[warp][lane] = s0 * inv;
        zrow[warp][lane + 32] = s1 * inv;
        __syncwarp();
        float oa = b21s[lane], ob = b21s[lane + 32];
#pragma unroll
        for (int cc = 0; cc < 64; cc++) {
            float z = zrow[warp][cc];
            oa = fmaf(z, W21s[cc * 64 + lane], oa);
            ob = fmaf(z, W21s[cc * 64 + lane + 32], ob);
        }
        oa = eluf(oa); ob = eluf(ob);
        orow[warp][lane] = oa;
        orow[warp][lane + 32] = ob;
        __syncwarp();
        float h = 0.f;
#pragma unroll
        for (int cc = 0; cc < 64; cc++) h = fmaf(orow[warp][cc], Wg2s[cc * 32 + lane], h);
        float p = h * a2ds[lane];
#pragma unroll
        for (int o = 16; o; o >>= 1) p += __shfl_xor_sync(0xFFFFFFFFu, p, o);
        float w2 = expf(p);
        int jl = warp * 2 + i;
        pst[lane][jl] = w2 * h;
        if (lane == 0) pst[32][jl] = w2;
        __syncwarp();
    }
    __syncthreads();
    for (int idx = tid; idx < 40 * 8; idx += 256) {
        int col = idx >> 3, u = idx & 7;
        float f0 = (col < 33) ? pst[col][2 * u] : 0.f;
        float f1 = (col < 33) ? pst[col][2 * u + 1] : 0.f;
        unsigned hw = (unsigned)__half_as_ushort(__float2half_rn(f0)) |
                      ((unsigned)__half_as_ushort(__float2half_rn(f1)) << 16);
        g_Pt2[col * (NN / 2) + blockIdx.x * 8 + permute8(u)] = hw;
    }
}

// -------- finalize layer2: o2 = elu(Z2@W22+b22), per-warp column sums -------
__global__ void k_fin2(const float* __restrict__ W22, const float* __restrict__ b22) {
    __shared__ float W22s[32 * 64], b22s[64];
    __shared__ float zr[8][32];
    int tid = threadIdx.x, lane = tid & 31, warp = tid >> 5;
    for (int i = tid; i < 2048; i += 256) W22s[i] = W22[i];
    if (tid < 64) b22s[tid] = b22[tid];
    __syncthreads();
    int wgl = blockIdx.x * 8 + warp;     // 0..511
    float aa = 0.f, ab = 0.f;
    for (int row = wgl; row < NN; row += 512) {
        float s = 0.f, sdp = 0.f;
#pragma unroll
        for (int k = 0; k < KSPLIT; k++) {
            const float* sp = g_S2p + ((long long)k * NN + row) * 40;
            s += sp[lane]; sdp += sp[32];
        }
        zr[warp][lane] = s / sdp;
        __syncwarp();
        float oa = b22s[lane], ob = b22s[lane + 32];
#pragma unroll
        for (int cc = 0; cc < 32; cc++) {
            float z = zr[warp][cc];
            oa = fmaf(z, W22s[cc * 64 + lane], oa);
            ob = fmaf(z, W22s[cc * 64 + lane + 32], ob);
        }
        aa += eluf(oa); ab += eluf(ob);
        __syncwarp();
    }
    g_gpart[(long long)wgl * 64 + lane] = aa;
    g_gpart[(long long)wgl * 64 + lane + 32] = ab;
}

// -------- head: parallel mean (256 thr, 4 groups) -> relu dense -> dense(2) -
__global__ void k_head(const float* __restrict__ M1, const float* __restrict__ bm1,
                       const float* __restrict__ M2, const float* __restrict__ bm2,
                       float* __restrict__ out) {
    __shared__ float part[4][64];
    __shared__ float gs[64], hs[64];
    int t = threadIdx.x;
    int col = t & 63, grp = t >> 6;              // 4 groups of 64 threads
    float s = 0.f;
    for (int w = grp; w < 512; w += 4) s += g_gpart[w * 64 + col];
    part[grp][col] = s;
    __syncthreads();
    if (t < 64) {
        gs[t] = ((part[0][t] + part[1][t]) + (part[2][t] + part[3][t])) * (1.f / 8192.f);
    }
    __syncthreads();
    if (t < 64) {
        float h = bm1[t];
        for (int cc = 0; cc < 64; cc++) h = fmaf(gs[cc], M1[cc * 64 + t], h);
        hs[t] = fmaxf(h, 0.f);
    }
    __syncthreads();
    if (t < 2) {
        float o = bm2[t];
        for (int cc = 0; cc < 64; cc++) o = fmaf(hs[cc], M2[cc * 2 + t], o);
        out[t] = o;
    }
}

extern "C" void kernel_launch(void* const* d_in, const int* in_sizes, int n_in,
                              void* d_out, int out_size) {
    const float* X   = (const float*)d_in[0];
    const int*   A   = (const int*)d_in[1];
    const float* W1  = (const float*)d_in[2];
    const float* a1  = (const float*)d_in[3];
    const float* W21 = (const float*)d_in[4];
    const float* b21 = (const float*)d_in[5];
    const float* Wg2 = (const float*)d_in[6];
    const float* a2  = (const float*)d_in[7];
    const float* W22 = (const float*)d_in[8];
    const float* b22 = (const float*)d_in[9];
    const float* M1  = (const float*)d_in[10];
    const float* bm1 = (const float*)d_in[11];
    const float* M2  = (const float*)d_in[12];
    const float* bm2 = (const float*)d_in[13];
    float* out = (float*)d_out;

    const int smem1 = 2 * 72 * 72 * (int)sizeof(unsigned);   // 41472 B
    const int smem2 = 2 * 40 * 72 * (int)sizeof(unsigned);   // 23040 B
    static bool attr_done = false;
    if (!attr_done) {
        cudaFuncSetAttribute(k_attn<1>, cudaFuncAttributeMaxDynamicSharedMemorySize, smem1);
        cudaFuncSetAttribute(k_attn<2>, cudaFuncAttributeMaxDynamicSharedMemorySize, smem2);
        attr_done = true;
    }

    k_packh1<<<2176, 256>>>(A, X, W1);     // h1 blocks first, pack overlapped
    k_buildP1<<<128, 256>>>(a1);
    k_attn<1><<<dim3(32, KSPLIT), 256, smem1>>>();
    k_fin1<<<512, 256>>>(W21, b21, Wg2, a2);
    k_attn<2><<<dim3(32, KSPLIT), 256, smem2>>>();
    k_fin2<<<64, 256>>>(W22, b22);
    k_head<<<1, 256>>>(M1, bm1, M2, bm2, out);
}

// round 16
// speedup vs baseline: 1.1298x; 1.0390x over previous
#include <cuda_runtime.h>
#include <cuda_bf16.h>
#include <cuda_fp16.h>

// ---------------------------------------------------------------------------
//   N=8192, DIN=768; layer1 dh=64 (P cols 65 -> pad 72), layer2 dh=32 (pad 40)
// Per GAT layer the softmax source-term cancels:
//   Z_i = (sum_j A_ij w_j H_j) / (sum_j A_ij w_j),  w_j = exp(H_j . a_dst)
// => one GEMM  S = A_bits @ [w*H | w]  per layer, single fp16 P, fp32 acc.
// P k-words PERMUTED within 8-word groups (p<4 -> 2p, else 2p-7) -> LDS.64.
// packh1: blocks 0-127 H1=X@W1 AND P1 build (H in registers, shfl-16
// reduction, pst aliases the GEMM staging smem -> total 17.2KB, so the
// pack branch keeps its 8-blocks/SM thread-cap residency);
// blocks 128-2175 pack A bits (wave-1 overlap of FMA-bound and HBM-bound).
// ---------------------------------------------------------------------------

#define NN 8192
#define KSPLIT 4

// -------- device scratch (static, no allocations) --------
__device__ uint4     g_Abits4[NN * 64];              // 8192 x 8192 bits, 8 MB
__device__ unsigned  g_Pt1[72 * (NN / 2)];           // P1 fp16 [72][8192] col-major (k-permuted)
__device__ unsigned  g_Pt2[40 * (NN / 2)];           // P2 fp16 (k-permuted)
__device__ float     g_S1p[KSPLIT * NN * 72];        // k-split partials, layer 1
__device__ float     g_S2p[KSPLIT * NN * 40];        // k-split partials, layer 2
__device__ float     g_gpart[512 * 64];              // per-warp sums for the mean

__device__ __forceinline__ float eluf(float x) { return x > 0.f ? x : expm1f(x); }

__device__ __forceinline__ int permute8(int u) {     // within 8-word group
    int p = u & 7;
    return (u & ~7) | ((p < 4) ? (2 * p) : (2 * p - 7));
}

__device__ __forceinline__ void cp_async16(void* dst, const void* src) {
    unsigned d = (unsigned)__cvta_generic_to_shared(dst);
    asm volatile("cp.async.cg.shared.global [%0], [%1], 16;\n" :: "r"(d), "l"(src));
}
__device__ __forceinline__ void cp_commit() {
    asm volatile("cp.async.commit_group;\n");
}
__device__ __forceinline__ void cp_wait1() {
    asm volatile("cp.async.wait_group 1;\n");
}

// -------- FUSED: blocks 0-127: H1=X@W1 then P1 (regs + aliased smem);
//          blocks 128-2175: pack A bits --------------------------------------
__global__ void __launch_bounds__(256) k_packh1(const int* __restrict__ A,
                                                const float* __restrict__ X,
                                                const float* __restrict__ W,
                                                const float* __restrict__ a1) {
    // union: GEMM staging (Xs 8448B + Ws 8192B = 16640B)  vs  pst (17160B)
    __shared__ __align__(16) char smbuf[65 * 66 * 4];
    float (*Xs)[33] = reinterpret_cast<float(*)[33]>(smbuf);
    float (*Ws)[64] = reinterpret_cast<float(*)[64]>(smbuf + 64 * 33 * 4);
    float (*pst)[66] = reinterpret_cast<float(*)[66]>(smbuf);
    int tid = threadIdx.x;

    if (blockIdx.x < 128) {
        // ---------------- H1 tile (compute-bound) ----------------
        int rb = blockIdx.x * 64;
        int tx = tid & 15;
        int ty = tid >> 4;
        float acc[4][4];
#pragma unroll
        for (int i = 0; i < 4; i++)
#pragma unroll
            for (int j = 0; j < 4; j++) acc[i][j] = 0.f;

        for (int k0 = 0; k0 < 768; k0 += 32) {
            {
                int r = tid >> 3;
                int c4 = (tid & 7) * 4;
#pragma unroll
                for (int i = 0; i < 2; i++) {
                    float4 v = *reinterpret_cast<const float4*>(
                        &X[(long long)(rb + r + i * 32) * 768 + k0 + c4]);
                    Xs[r + i * 32][c4 + 0] = v.x; Xs[r + i * 32][c4 + 1] = v.y;
                    Xs[r + i * 32][c4 + 2] = v.z; Xs[r + i * 32][c4 + 3] = v.w;
                }
#pragma unroll
                for (int i = 0; i < 2; i++) {
                    int kk = (tid >> 4) + i * 16;
                    float4 v = *reinterpret_cast<const float4*>(
                        &W[(long long)(k0 + kk) * 64 + (tid & 15) * 4]);
                    Ws[kk][(tid & 15) * 4 + 0] = v.x; Ws[kk][(tid & 15) * 4 + 1] = v.y;
                    Ws[kk][(tid & 15) * 4 + 2] = v.z; Ws[kk][(tid & 15) * 4 + 3] = v.w;
                }
            }
            __syncthreads();
#pragma unroll
            for (int kk = 0; kk < 32; kk++) {
                float b0 = Ws[kk][tx * 4 + 0], b1 = Ws[kk][tx * 4 + 1];
                float b2 = Ws[kk][tx * 4 + 2], b3 = Ws[kk][tx * 4 + 3];
#pragma unroll
                for (int i = 0; i < 4; i++) {
                    float a = Xs[ty * 4 + i][kk];
                    acc[i][0] = fmaf(a, b0, acc[i][0]);
                    acc[i][1] = fmaf(a, b1, acc[i][1]);
                    acc[i][2] = fmaf(a, b2, acc[i][2]);
                    acc[i][3] = fmaf(a, b3, acc[i][3]);
                }
            }
            __syncthreads();               // last read of Xs/Ws before aliasing
        }

        // ---------------- P1 build: H in registers ----------------
        // thread (ty, tx) holds H[rb + ty*4+i][tx*4+j] = acc[i][j].
        float ad[4];
#pragma unroll
        for (int j = 0; j < 4; j++) ad[j] = a1[64 + tx * 4 + j];
#pragma unroll
        for (int i = 0; i < 4; i++) {
            float p = acc[i][0] * ad[0] + acc[i][1] * ad[1] +
                      acc[i][2] * ad[2] + acc[i][3] * ad[3];
#pragma unroll
            for (int o = 8; o; o >>= 1) p += __shfl_xor_sync(0xFFFFFFFFu, p, o);
            float w = expf(p);             // all 16 lanes of the group agree
            int r = ty * 4 + i;
#pragma unroll
            for (int j = 0; j < 4; j++) pst[tx * 4 + j][r] = w * acc[i][j];
            if (tx == 0) pst[64][r] = w;
        }
        __syncthreads();
        for (int idx = tid; idx < 72 * 32; idx += 256) {
            int col = idx >> 5, u = idx & 31;
            float f0 = (col < 65) ? pst[col][2 * u] : 0.f;
            float f1 = (col < 65) ? pst[col][2 * u + 1] : 0.f;
            unsigned hw = (unsigned)__half_as_ushort(__float2half_rn(f0)) |
                          ((unsigned)__half_as_ushort(__float2half_rn(f1)) << 16);
            g_Pt1[col * (NN / 2) + blockIdx.x * 32 + permute8(u)] = hw;
        }
    } else {
        // ---------------- pack A into bits (HBM-bound) ----------------
        unsigned* bits = reinterpret_cast<unsigned*>(g_Abits4);
        int bid = blockIdx.x - 128;
        int warp = (bid * 256 + tid) >> 5;
        int lane = tid & 31;
        const int nwarps = (2048 * 256) >> 5;
        const int ngroups = (NN * (NN / 32)) / 8;
        for (int g = warp; g < ngroups; g += nwarps) {
            long long base = (long long)g * 256 + lane;
            int v[8];
#pragma unroll
            for (int i = 0; i < 8; i++) v[i] = A[base + i * 32];
#pragma unroll
            for (int i = 0; i < 8; i++) {
                unsigned m = __ballot_sync(0xFFFFFFFFu, v[i] != 0);
                if (lane == 0) bits[g * 8 + i] = m;
            }
        }
    }
}

// -------- fp16 mma helper --------
__device__ __forceinline__ void mma16816_f16(float (&d)[4], unsigned a0, unsigned a1,
                                             unsigned a2, unsigned a3, unsigned b0, unsigned b1) {
    asm volatile(
        "mma.sync.aligned.m16n8k16.row.col.f32.f16.f16.f32 "
        "{%0,%1,%2,%3}, {%4,%5,%6,%7}, {%8,%9}, {%0,%1,%2,%3};\n"
        : "+f"(d[0]), "+f"(d[1]), "+f"(d[2]), "+f"(d[3])
        : "r"(a0), "r"(a1), "r"(a2), "r"(a3), "r"(b0), "r"(b1));
}

// -------- S = A_bits @ P : m=32/warp, cp.async double buffer, fp16 ----------
// grid (32 m-tiles of 256 rows, 4 k-splits), 256 threads.
template <int LAYER>
__global__ void __launch_bounds__(256, 2) k_attn() {
    constexpr int NT = (LAYER == 1) ? 9 : 5;
    constexpr int CPAD = NT * 8;
    constexpr int TW = CPAD * 72;                 // u32 per stage
    const unsigned* __restrict__ Pt = (LAYER == 1) ? g_Pt1 : g_Pt2;
    float* __restrict__ Sp = (LAYER == 1) ? g_S1p : g_S2p;

    extern __shared__ unsigned sB[];              // [stage][TW]

    int tid = threadIdx.x, lane = tid & 31, warp = tid >> 5;
    int g = lane >> 2, c = lane & 3;
    int R = blockIdx.x * 256 + warp * 32;

    float acc0[NT][4], acc1[NT][4];
#pragma unroll
    for (int t = 0; t < NT; t++)
#pragma unroll
        for (int i = 0; i < 4; i++) { acc0[t][i] = 0.f; acc1[t][i] = 0.f; }

    const int ch0 = blockIdx.y * 16;              // 16 chunks of k=128 per split

    auto pk = [](unsigned t) -> unsigned {        // 2 bits -> fp16x2 of {0,1}
        return ((t & 1u) | ((t << 15) & 0x10000u)) * 0x3C00u;
    };
    auto issue_stage = [&](int st, int ch) {
        int koff = ch * 64;                        // u32 offset along k
        unsigned* dsh = sB + st * TW;
        for (int i = tid; i < CPAD * 16; i += 256) {
            int n = i >> 4, kc = (i & 15) * 4;
            cp_async16(&dsh[n * 72 + kc], &Pt[n * (NN / 2) + koff + kc]);
        }
    };

    issue_stage(0, ch0);
    cp_commit();
    uint4 nb0 = g_Abits4[(long long)(R + g) * 64 + ch0];
    uint4 nb1 = g_Abits4[(long long)(R + 8 + g) * 64 + ch0];
    uint4 nb2 = g_Abits4[(long long)(R + 16 + g) * 64 + ch0];
    uint4 nb3 = g_Abits4[(long long)(R + 24 + g) * 64 + ch0];

    for (int kk = 0; kk < 16; kk++) {
        uint4 b0 = nb0, b1 = nb1, b2 = nb2, b3 = nb3;
        if (kk + 1 < 16) issue_stage((kk + 1) & 1, ch0 + kk + 1);
        cp_commit();
        if (kk + 1 < 16) {
            int ch = ch0 + kk + 1;
            nb0 = g_Abits4[(long long)(R + g) * 64 + ch];
            nb1 = g_Abits4[(long long)(R + 8 + g) * 64 + ch];
            nb2 = g_Abits4[(long long)(R + 16 + g) * 64 + ch];
            nb3 = g_Abits4[(long long)(R + 24 + g) * 64 + ch];
        }
        cp_wait1();
        __syncthreads();

        const unsigned* bh = sB + (kk & 1) * TW;
        unsigned w0[4] = {b0.x, b0.y, b0.z, b0.w};
        unsigned w1[4] = {b1.x, b1.y, b1.z, b1.w};
        unsigned w2[4] = {b2.x, b2.y, b2.z, b2.w};
        unsigned w3[4] = {b3.x, b3.y, b3.z, b3.w};
#pragma unroll
        for (int s = 0; s < 8; s++) {
            int sh = (s & 1) * 16 + 2 * c;
            unsigned t0 = w0[s >> 1] >> sh;
            unsigned t1 = w1[s >> 1] >> sh;
            unsigned t2 = w2[s >> 1] >> sh;
            unsigned t3 = w3[s >> 1] >> sh;
            unsigned a0 = pk(t0), a1r = pk(t1);
            unsigned a2 = pk(t0 >> 8), a3 = pk(t1 >> 8);
            unsigned e0 = pk(t2), e1 = pk(t3);
            unsigned e2 = pk(t2 >> 8), e3 = pk(t3 >> 8);
#pragma unroll
            for (int t = 0; t < NT; t++) {
                int bi = (t * 8 + g) * 72 + s * 8 + 2 * c;
                uint2 bb = *reinterpret_cast<const uint2*>(&bh[bi]);
                mma16816_f16(acc0[t], a0, a1r, a2, a3, bb.x, bb.y);
                mma16816_f16(acc1[t], e0, e1, e2, e3, bb.x, bb.y);
            }
        }
        __syncthreads();
    }

    float* so = Sp + ((long long)blockIdx.y * NN + R + g) * CPAD;
#pragma unroll
    for (int t = 0; t < NT; t++) {
        int col = t * 8 + 2 * c;
        so[col] = acc0[t][0];
        so[col + 1] = acc0[t][1];
        so[8 * CPAD + col] = acc0[t][2];
        so[8 * CPAD + col + 1] = acc0[t][3];
        so[16 * CPAD + col] = acc1[t][0];
        so[16 * CPAD + col + 1] = acc1[t][1];
        so[24 * CPAD + col] = acc1[t][2];
        so[24 * CPAD + col + 1] = acc1[t][3];
    }
}

// -------- finalize layer1 -> P2 (fp16, k-permuted), 16 rows/block, 512 blks -
__global__ void k_fin1(const float* __restrict__ W21, const float* __restrict__ b21,
                       const float* __restrict__ Wg2, const float* __restrict__ a2) {
    __shared__ float W21s[64 * 64], Wg2s[64 * 32], b21s[64], a2ds[32];
    __shared__ float zrow[8][64], orow[8][64];
    __shared__ float pst[33][18];
    int tid = threadIdx.x, lane = tid & 31, warp = tid >> 5;
    int base = blockIdx.x * 16;
    for (int i = tid; i < 4096; i += 256) W21s[i] = W21[i];
    for (int i = tid; i < 2048; i += 256) Wg2s[i] = Wg2[i];
    if (tid < 64) b21s[tid] = b21[tid];
    if (tid < 32) a2ds[tid] = a2[32 + tid];
    __syncthreads();

#pragma unroll
    for (int i = 0; i < 2; i++) {
        int row = base + warp * 2 + i;
        float s0 = 0.f, s1 = 0.f, sd = 0.f;
#pragma unroll
        for (int k = 0; k < KSPLIT; k++) {
            const float* sp = g_S1p + ((long long)k * NN + row) * 72;
            s0 += sp[lane]; s1 += sp[lane + 32]; sd += sp[64];
        }
        float inv = 1.f / sd;
        zrow[warp][lane] = s0 * inv;
        zrow[warp][lane + 32] = s1 * inv;
        __syncwarp();
        float oa = b21s[lane], ob = b21s[lane + 32];
#pragma unroll
        for (int cc = 0; cc < 64; cc++) {
            float z = zrow[warp][cc];
            oa = fmaf(z, W21s[cc * 64 + lane], oa);
            ob = fmaf(z, W21s[cc * 64 + lane + 32], ob);
        }
        oa = eluf(oa); ob = eluf(ob);
        orow[warp][lane] = oa;
        orow[warp][lane + 32] = ob;
        __syncwarp();
        float h = 0.f;
#pragma unroll
        for (int cc = 0; cc < 64; cc++) h = fmaf(orow[warp][cc], Wg2s[cc * 32 + lane], h);
        float p = h * a2ds[lane];
#pragma unroll
        for (int o = 16; o; o >>= 1) p += __shfl_xor_sync(0xFFFFFFFFu, p, o);
        float w2 = expf(p);
        int jl = warp * 2 + i;
        pst[lane][jl] = w2 * h;
        if (lane == 0) pst[32][jl] = w2;
        __syncwarp();
    }
    __syncthreads();
    for (int idx = tid; idx < 40 * 8; idx += 256) {
        int col = idx >> 3, u = idx & 7;
        float f0 = (col < 33) ? pst[col][2 * u] : 0.f;
        float f1 = (col < 33) ? pst[col][2 * u + 1] : 0.f;
        unsigned hw = (unsigned)__half_as_ushort(__float2half_rn(f0)) |
                      ((unsigned)__half_as_ushort(__float2half_rn(f1)) << 16);
        g_Pt2[col * (NN / 2) + blockIdx.x * 8 + permute8(u)] = hw;
    }
}

// -------- finalize layer2: o2 = elu(Z2@W22+b22), per-warp column sums -------
__global__ void k_fin2(const float* __restrict__ W22, const float* __restrict__ b22) {
    __shared__ float W22s[32 * 64], b22s[64];
    __shared__ float zr[8][32];
    int tid = threadIdx.x, lane = tid & 31, warp = tid >> 5;
    for (int i = tid; i < 2048; i += 256) W22s[i] = W22[i];
    if (tid < 64) b22s[tid] = b22[tid];
    __syncthreads();
    int wgl = blockIdx.x * 8 + warp;     // 0..511
    float aa = 0.f, ab = 0.f;
    for (int row = wgl; row < NN; row += 512) {
        float s = 0.f, sdp = 0.f;
#pragma unroll
        for (int k = 0; k < KSPLIT; k++) {
            const float* sp = g_S2p + ((long long)k * NN + row) * 40;
            s += sp[lane]; sdp += sp[32];
        }
        zr[warp][lane] = s / sdp;
        __syncwarp();
        float oa = b22s[lane], ob = b22s[lane + 32];
#pragma unroll
        for (int cc = 0; cc < 32; cc++) {
            float z = zr[warp][cc];
            oa = fmaf(z, W22s[cc * 64 + lane], oa);
            ob = fmaf(z, W22s[cc * 64 + lane + 32], ob);
        }
        aa += eluf(oa); ab += eluf(ob);
        __syncwarp();
    }
    g_gpart[(long long)wgl * 64 + lane] = aa;
    g_gpart[(long long)wgl * 64 + lane + 32] = ab;
}

// -------- head: parallel mean (256 thr, 4 groups) -> relu dense -> dense(2) -
__global__ void k_head(const float* __restrict__ M1, const float* __restrict__ bm1,
                       const float* __restrict__ M2, const float* __restrict__ bm2,
                       float* __restrict__ out) {
    __shared__ float part[4][64];
    __shared__ float gs[64], hs[64];
    int t = threadIdx.x;
    int col = t & 63, grp = t >> 6;              // 4 groups of 64 threads
    float s = 0.f;
    for (int w = grp; w < 512; w += 4) s += g_gpart[w * 64 + col];
    part[grp][col] = s;
    __syncthreads();
    if (t < 64) {
        gs[t] = ((part[0][t] + part[1][t]) + (part[2][t] + part[3][t])) * (1.f / 8192.f);
    }
    __syncthreads();
    if (t < 64) {
        float h = bm1[t];
        for (int cc = 0; cc < 64; cc++) h = fmaf(gs[cc], M1[cc * 64 + t], h);
        hs[t] = fmaxf(h, 0.f);
    }
    __syncthreads();
    if (t < 2) {
        float o = bm2[t];
        for (int cc = 0; cc < 64; cc++) o = fmaf(hs[cc], M2[cc * 2 + t], o);
        out[t] = o;
    }
}

extern "C" void kernel_launch(void* const* d_in, const int* in_sizes, int n_in,
                              void* d_out, int out_size) {
    const float* X   = (const float*)d_in[0];
    const int*   A   = (const int*)d_in[1];
    const float* W1  = (const float*)d_in[2];
    const float* a1  = (const float*)d_in[3];
    const float* W21 = (const float*)d_in[4];
    const float* b21 = (const float*)d_in[5];
    const float* Wg2 = (const float*)d_in[6];
    const float* a2  = (const float*)d_in[7];
    const float* W22 = (const float*)d_in[8];
    const float* b22 = (const float*)d_in[9];
    const float* M1  = (const float*)d_in[10];
    const float* bm1 = (const float*)d_in[11];
    const float* M2  = (const float*)d_in[12];
    const float* bm2 = (const float*)d_in[13];
    float* out = (float*)d_out;

    const int smem1 = 2 * 72 * 72 * (int)sizeof(unsigned);   // 41472 B
    const int smem2 = 2 * 40 * 72 * (int)sizeof(unsigned);   // 23040 B
    static bool attr_done = false;
    if (!attr_done) {
        cudaFuncSetAttribute(k_attn<1>, cudaFuncAttributeMaxDynamicSharedMemorySize, smem1);
        cudaFuncSetAttribute(k_attn<2>, cudaFuncAttributeMaxDynamicSharedMemorySize, smem2);
        attr_done = true;
    }

    k_packh1<<<2176, 256>>>(A, X, W1, a1);   // h1+P1 blocks first, pack overlapped
    k_attn<1><<<dim3(32, KSPLIT), 256, smem1>>>();
    k_fin1<<<512, 256>>>(W21, b21, Wg2, a2);
    k_attn<2><<<dim3(32, KSPLIT), 256, smem2>>>();
    k_fin2<<<64, 256>>>(W22, b22);
    k_head<<<1, 256>>>(M1, bm1, M2, bm2, out);
}

// round 17
// speedup vs baseline: 1.1426x; 1.0113x over previous
#include <cuda_runtime.h>
#include <cuda_bf16.h>
#include <cuda_fp16.h>

// ---------------------------------------------------------------------------
//   N=8192, DIN=768; layer1 dh=64 (P cols 65 -> pad 72), layer2 dh=32 (pad 40)
// Per GAT layer the softmax source-term cancels:
//   Z_i = (sum_j A_ij w_j H_j) / (sum_j A_ij w_j),  w_j = exp(H_j . a_dst)
// => one GEMM  S = A_bits @ [w*H | w]  per layer, single fp16 P, fp32 acc.
// P k-words PERMUTED within 8-word groups (p<4 -> 2p, else 2p-7) -> LDS.64.
// packh1: blocks 0-127 H1=X@W1 AND P1 build (H in registers, aliased smem);
// blocks 128-2175 pack A bits (wave-1 overlap).
// THIS ROUND (vs R16 best): attn uses a 3-stage cp.async ring with ONE
// __syncthreads per k-chunk (barrier after wait publishes stage kk AND
// retires stage kk-1 before its buffer is re-targeted at kk+2).
// ---------------------------------------------------------------------------

#define NN 8192
#define KSPLIT 4

// -------- device scratch (static, no allocations) --------
__device__ uint4     g_Abits4[NN * 64];              // 8192 x 8192 bits, 8 MB
__device__ unsigned  g_Pt1[72 * (NN / 2)];           // P1 fp16 [72][8192] col-major (k-permuted)
__device__ unsigned  g_Pt2[40 * (NN / 2)];           // P2 fp16 (k-permuted)
__device__ float     g_S1p[KSPLIT * NN * 72];        // k-split partials, layer 1
__device__ float     g_S2p[KSPLIT * NN * 40];        // k-split partials, layer 2
__device__ float     g_gpart[512 * 64];              // per-warp sums for the mean

__device__ __forceinline__ float eluf(float x) { return x > 0.f ? x : expm1f(x); }

__device__ __forceinline__ int permute8(int u) {     // within 8-word group
    int p = u & 7;
    return (u & ~7) | ((p < 4) ? (2 * p) : (2 * p - 7));
}

__device__ __forceinline__ void cp_async16(void* dst, const void* src) {
    unsigned d = (unsigned)__cvta_generic_to_shared(dst);
    asm volatile("cp.async.cg.shared.global [%0], [%1], 16;\n" :: "r"(d), "l"(src));
}
__device__ __forceinline__ void cp_commit() {
    asm volatile("cp.async.commit_group;\n");
}
__device__ __forceinline__ void cp_wait1() {
    asm volatile("cp.async.wait_group 1;\n");
}

// -------- FUSED: blocks 0-127: H1=X@W1 then P1 (regs + aliased smem);
//          blocks 128-2175: pack A bits --------------------------------------
__global__ void __launch_bounds__(256) k_packh1(const int* __restrict__ A,
                                                const float* __restrict__ X,
                                                const float* __restrict__ W,
                                                const float* __restrict__ a1) {
    // union: GEMM staging (Xs 8448B + Ws 8192B = 16640B)  vs  pst (17160B)
    __shared__ __align__(16) char smbuf[65 * 66 * 4];
    float (*Xs)[33] = reinterpret_cast<float(*)[33]>(smbuf);
    float (*Ws)[64] = reinterpret_cast<float(*)[64]>(smbuf + 64 * 33 * 4);
    float (*pst)[66] = reinterpret_cast<float(*)[66]>(smbuf);
    int tid = threadIdx.x;

    if (blockIdx.x < 128) {
        // ---------------- H1 tile (compute-bound) ----------------
        int rb = blockIdx.x * 64;
        int tx = tid & 15;
        int ty = tid >> 4;
        float acc[4][4];
#pragma unroll
        for (int i = 0; i < 4; i++)
#pragma unroll
            for (int j = 0; j < 4; j++) acc[i][j] = 0.f;

        for (int k0 = 0; k0 < 768; k0 += 32) {
            {
                int r = tid >> 3;
                int c4 = (tid & 7) * 4;
#pragma unroll
                for (int i = 0; i < 2; i++) {
                    float4 v = *reinterpret_cast<const float4*>(
                        &X[(long long)(rb + r + i * 32) * 768 + k0 + c4]);
                    Xs[r + i * 32][c4 + 0] = v.x; Xs[r + i * 32][c4 + 1] = v.y;
                    Xs[r + i * 32][c4 + 2] = v.z; Xs[r + i * 32][c4 + 3] = v.w;
                }
#pragma unroll
                for (int i = 0; i < 2; i++) {
                    int kk = (tid >> 4) + i * 16;
                    float4 v = *reinterpret_cast<const float4*>(
                        &W[(long long)(k0 + kk) * 64 + (tid & 15) * 4]);
                    Ws[kk][(tid & 15) * 4 + 0] = v.x; Ws[kk][(tid & 15) * 4 + 1] = v.y;
                    Ws[kk][(tid & 15) * 4 + 2] = v.z; Ws[kk][(tid & 15) * 4 + 3] = v.w;
                }
            }
            __syncthreads();
#pragma unroll
            for (int kk = 0; kk < 32; kk++) {
                float b0 = Ws[kk][tx * 4 + 0], b1 = Ws[kk][tx * 4 + 1];
                float b2 = Ws[kk][tx * 4 + 2], b3 = Ws[kk][tx * 4 + 3];
#pragma unroll
                for (int i = 0; i < 4; i++) {
                    float a = Xs[ty * 4 + i][kk];
                    acc[i][0] = fmaf(a, b0, acc[i][0]);
                    acc[i][1] = fmaf(a, b1, acc[i][1]);
                    acc[i][2] = fmaf(a, b2, acc[i][2]);
                    acc[i][3] = fmaf(a, b3, acc[i][3]);
                }
            }
            __syncthreads();               // last read of Xs/Ws before aliasing
        }

        // ---------------- P1 build: H in registers ----------------
        float ad[4];
#pragma unroll
        for (int j = 0; j < 4; j++) ad[j] = a1[64 + tx * 4 + j];
#pragma unroll
        for (int i = 0; i < 4; i++) {
            float p = acc[i][0] * ad[0] + acc[i][1] * ad[1] +
                      acc[i][2] * ad[2] + acc[i][3] * ad[3];
#pragma unroll
            for (int o = 8; o; o >>= 1) p += __shfl_xor_sync(0xFFFFFFFFu, p, o);
            float w = expf(p);
            int r = ty * 4 + i;
#pragma unroll
            for (int j = 0; j < 4; j++) pst[tx * 4 + j][r] = w * acc[i][j];
            if (tx == 0) pst[64][r] = w;
        }
        __syncthreads();
        for (int idx = tid; idx < 72 * 32; idx += 256) {
            int col = idx >> 5, u = idx & 31;
            float f0 = (col < 65) ? pst[col][2 * u] : 0.f;
            float f1 = (col < 65) ? pst[col][2 * u + 1] : 0.f;
            unsigned hw = (unsigned)__half_as_ushort(__float2half_rn(f0)) |
                          ((unsigned)__half_as_ushort(__float2half_rn(f1)) << 16);
            g_Pt1[col * (NN / 2) + blockIdx.x * 32 + permute8(u)] = hw;
        }
    } else {
        // ---------------- pack A into bits (HBM-bound) ----------------
        unsigned* bits = reinterpret_cast<unsigned*>(g_Abits4);
        int bid = blockIdx.x - 128;
        int warp = (bid * 256 + tid) >> 5;
        int lane = tid & 31;
        const int nwarps = (2048 * 256) >> 5;
        const int ngroups = (NN * (NN / 32)) / 8;
        for (int g = warp; g < ngroups; g += nwarps) {
            long long base = (long long)g * 256 + lane;
            int v[8];
#pragma unroll
            for (int i = 0; i < 8; i++) v[i] = A[base + i * 32];
#pragma unroll
            for (int i = 0; i < 8; i++) {
                unsigned m = __ballot_sync(0xFFFFFFFFu, v[i] != 0);
                if (lane == 0) bits[g * 8 + i] = m;
            }
        }
    }
}

// -------- fp16 mma helper --------
__device__ __forceinline__ void mma16816_f16(float (&d)[4], unsigned a0, unsigned a1,
                                             unsigned a2, unsigned a3, unsigned b0, unsigned b1) {
    asm volatile(
        "mma.sync.aligned.m16n8k16.row.col.f32.f16.f16.f32 "
        "{%0,%1,%2,%3}, {%4,%5,%6,%7}, {%8,%9}, {%0,%1,%2,%3};\n"
        : "+f"(d[0]), "+f"(d[1]), "+f"(d[2]), "+f"(d[3])
        : "r"(a0), "r"(a1), "r"(a2), "r"(a3), "r"(b0), "r"(b1));
}

// -------- S = A_bits @ P : m=32/warp, 3-stage cp.async ring, fp16 -----------
// grid (32 m-tiles of 256 rows, 4 k-splits), 256 threads.
// ONE __syncthreads per chunk: barrier after wait publishes stage kk AND
// retires stage kk-1 (== stage (kk+2)%3, the next cp.async target).
template <int LAYER>
__global__ void __launch_bounds__(256, 2) k_attn() {
    constexpr int NT = (LAYER == 1) ? 9 : 5;
    constexpr int CPAD = NT * 8;
    constexpr int TW = CPAD * 72;                 // u32 per stage
    const unsigned* __restrict__ Pt = (LAYER == 1) ? g_Pt1 : g_Pt2;
    float* __restrict__ Sp = (LAYER == 1) ? g_S1p : g_S2p;

    extern __shared__ unsigned sB[];              // [3][TW]

    int tid = threadIdx.x, lane = tid & 31, warp = tid >> 5;
    int g = lane >> 2, c = lane & 3;
    int R = blockIdx.x * 256 + warp * 32;

    float acc0[NT][4], acc1[NT][4];
#pragma unroll
    for (int t = 0; t < NT; t++)
#pragma unroll
        for (int i = 0; i < 4; i++) { acc0[t][i] = 0.f; acc1[t][i] = 0.f; }

    const int ch0 = blockIdx.y * 16;              // 16 chunks of k=128 per split

    auto pk = [](unsigned t) -> unsigned {        // 2 bits -> fp16x2 of {0,1}
        return ((t & 1u) | ((t << 15) & 0x10000u)) * 0x3C00u;
    };
    auto issue_stage = [&](int st, int ch) {
        int koff = ch * 64;                        // u32 offset along k
        unsigned* dsh = sB + st * TW;
        for (int i = tid; i < CPAD * 16; i += 256) {
            int n = i >> 4, kc = (i & 15) * 4;
            cp_async16(&dsh[n * 72 + kc], &Pt[n * (NN / 2) + koff + kc]);
        }
    };

    issue_stage(0, ch0);
    cp_commit();
    issue_stage(1, ch0 + 1);
    cp_commit();
    uint4 nb0 = g_Abits4[(long long)(R + g) * 64 + ch0];
    uint4 nb1 = g_Abits4[(long long)(R + 8 + g) * 64 + ch0];
    uint4 nb2 = g_Abits4[(long long)(R + 16 + g) * 64 + ch0];
    uint4 nb3 = g_Abits4[(long long)(R + 24 + g) * 64 + ch0];

    for (int kk = 0; kk < 16; kk++) {
        uint4 b0 = nb0, b1 = nb1, b2 = nb2, b3 = nb3;
        cp_wait1();                                // stage kk arrived
        __syncthreads();                           // publish kk; retire kk-1
        if (kk + 2 < 16) issue_stage((kk + 2) % 3, ch0 + kk + 2);
        cp_commit();
        if (kk + 1 < 16) {
            int ch = ch0 + kk + 1;
            nb0 = g_Abits4[(long long)(R + g) * 64 + ch];
            nb1 = g_Abits4[(long long)(R + 8 + g) * 64 + ch];
            nb2 = g_Abits4[(long long)(R + 16 + g) * 64 + ch];
            nb3 = g_Abits4[(long long)(R + 24 + g) * 64 + ch];
        }

        const unsigned* bh = sB + (kk % 3) * TW;
        unsigned w0[4] = {b0.x, b0.y, b0.z, b0.w};
        unsigned w1[4] = {b1.x, b1.y, b1.z, b1.w};
        unsigned w2[4] = {b2.x, b2.y, b2.z, b2.w};
        unsigned w3[4] = {b3.x, b3.y, b3.z, b3.w};
#pragma unroll
        for (int s = 0; s < 8; s++) {
            int sh = (s & 1) * 16 + 2 * c;
            unsigned t0 = w0[s >> 1] >> sh;
            unsigned t1 = w1[s >> 1] >> sh;
            unsigned t2 = w2[s >> 1] >> sh;
            unsigned t3 = w3[s >> 1] >> sh;
            unsigned a0 = pk(t0), a1r = pk(t1);
            unsigned a2 = pk(t0 >> 8), a3 = pk(t1 >> 8);
            unsigned e0 = pk(t2), e1 = pk(t3);
            unsigned e2 = pk(t2 >> 8), e3 = pk(t3 >> 8);
#pragma unroll
            for (int t = 0; t < NT; t++) {
                int bi = (t * 8 + g) * 72 + s * 8 + 2 * c;
                uint2 bb = *reinterpret_cast<const uint2*>(&bh[bi]);
                mma16816_f16(acc0[t], a0, a1r, a2, a3, bb.x, bb.y);
                mma16816_f16(acc1[t], e0, e1, e2, e3, bb.x, bb.y);
            }
        }
    }

    float* so = Sp + ((long long)blockIdx.y * NN + R + g) * CPAD;
#pragma unroll
    for (int t = 0; t < NT; t++) {
        int col = t * 8 + 2 * c;
        so[col] = acc0[t][0];
        so[col + 1] = acc0[t][1];
        so[8 * CPAD + col] = acc0[t][2];
        so[8 * CPAD + col + 1] = acc0[t][3];
        so[16 * CPAD + col] = acc1[t][0];
        so[16 * CPAD + col + 1] = acc1[t][1];
        so[24 * CPAD + col] = acc1[t][2];
        so[24 * CPAD + col + 1] = acc1[t][3];
    }
}

// -------- finalize layer1 -> P2 (fp16, k-permuted), 16 rows/block, 512 blks -
__global__ void k_fin1(const float* __restrict__ W21, const float* __restrict__ b21,
                       const float* __restrict__ Wg2, const float* __restrict__ a2) {
    __shared__ float W21s[64 * 64], Wg2s[64 * 32], b21s[64], a2ds[32];
    __shared__ float zrow[8][64], orow[8][64];
    __shared__ float pst[33][18];
    int tid = threadIdx.x, lane = tid & 31, warp = tid >> 5;
    int base = blockIdx.x * 16;
    for (int i = tid; i < 4096; i += 256) W21s[i] = W21[i];
    for (int i = tid; i < 2048; i += 256) Wg2s[i] = Wg2[i];
    if (tid < 64) b21s[tid] = b21[tid];
    if (tid < 32) a2ds[tid] = a2[32 + tid];
    __syncthreads();

#pragma unroll
    for (int i = 0; i < 2; i++) {
        int row = base + warp * 2 + i;
        float s0 = 0.f, s1 = 0.f, sd = 0.f;
#pragma unroll
        for (int k = 0; k < KSPLIT; k++) {
            const float* sp = g_S1p + ((long long)k * NN + row) * 72;
            s0 += sp[lane]; s1 += sp[lane + 32]; sd += sp[64];
        }
        float inv = 1.f / sd;
        zrow[warp][lane] = s0 * inv;
        zrow[warp][lane + 32] = s1 * inv;
        __syncwarp();
        float oa = b21s[lane], ob = b21s[lane + 32];
#pragma unroll
        for (int cc = 0; cc < 64; cc++) {
            float z = zrow[warp][cc];
            oa = fmaf(z, W21s[cc * 64 + lane], oa);
            ob = fmaf(z, W21s[cc * 64 + lane + 32], ob);
        }
        oa = eluf(oa); ob = eluf(ob);
        orow[warp][lane] = oa;
        orow[warp][lane + 32] = ob;
        __syncwarp();
        float h = 0.f;
#pragma unroll
        for (int cc = 0; cc < 64; cc++) h = fmaf(orow[warp][cc], Wg2s[cc * 32 + lane], h);
        float p = h * a2ds[lane];
#pragma unroll
        for (int o = 16; o; o >>= 1) p += __shfl_xor_sync(0xFFFFFFFFu, p, o);
        float w2 = expf(p);
        int jl = warp * 2 + i;
        pst[lane][jl] = w2 * h;
        if (lane == 0) pst[32][jl] = w2;
        __syncwarp();
    }
    __syncthreads();
    for (int idx = tid; idx < 40 * 8; idx += 256) {
        int col = idx >> 3, u = idx & 7;
        float f0 = (col < 33) ? pst[col][2 * u] : 0.f;
        float f1 = (col < 33) ? pst[col][2 * u + 1] : 0.f;
        unsigned hw = (unsigned)__half_as_ushort(__float2half_rn(f0)) |
                      ((unsigned)__half_as_ushort(__float2half_rn(f1)) << 16);
        g_Pt2[col * (NN / 2) + blockIdx.x * 8 + permute8(u)] = hw;
    }
}

// -------- finalize layer2: o2 = elu(Z2@W22+b22), per-warp column sums -------
__global__ void k_fin2(const float* __restrict__ W22, const float* __restrict__ b22) {
    __shared__ float W22s[32 * 64], b22s[64];
    __shared__ float zr[8][32];
    int tid = threadIdx.x, lane = tid & 31, warp = tid >> 5;
    for (int i = tid; i < 2048; i += 256) W22s[i] = W22[i];
    if (tid < 64) b22s[tid] = b22[tid];
    __syncthreads();
    int wgl = blockIdx.x * 8 + warp;     // 0..511
    float aa = 0.f, ab = 0.f;
    for (int row = wgl; row < NN; row += 512) {
        float s = 0.f, sdp = 0.f;
#pragma unroll
        for (int k = 0; k < KSPLIT; k++) {
            const float* sp = g_S2p + ((long long)k * NN + row) * 40;
            s += sp[lane]; sdp += sp[32];
        }
        zr[warp][lane] = s / sdp;
        __syncwarp();
        float oa = b22s[lane], ob = b22s[lane + 32];
#pragma unroll
        for (int cc = 0; cc < 32; cc++) {
            float z = zr[warp][cc];
            oa = fmaf(z, W22s[cc * 64 + lane], oa);
            ob = fmaf(z, W22s[cc * 64 + lane + 32], ob);
        }
        aa += eluf(oa); ab += eluf(ob);
        __syncwarp();
    }
    g_gpart[(long long)wgl * 64 + lane] = aa;
    g_gpart[(long long)wgl * 64 + lane + 32] = ab;
}

// -------- head: parallel mean (256 thr, 4 groups) -> relu dense -> dense(2) -
__global__ void k_head(const float* __restrict__ M1, const float* __restrict__ bm1,
                       const float* __restrict__ M2, const float* __restrict__ bm2,
                       float* __restrict__ out) {
    __shared__ float part[4][64];
    __shared__ float gs[64], hs[64];
    int t = threadIdx.x;
    int col = t & 63, grp = t >> 6;              // 4 groups of 64 threads
    float s = 0.f;
    for (int w = grp; w < 512; w += 4) s += g_gpart[w * 64 + col];
    part[grp][col] = s;
    __syncthreads();
    if (t < 64) {
        gs[t] = ((part[0][t] + part[1][t]) + (part[2][t] + part[3][t])) * (1.f / 8192.f);
    }
    __syncthreads();
    if (t < 64) {
        float h = bm1[t];
        for (int cc = 0; cc < 64; cc++) h = fmaf(gs[cc], M1[cc * 64 + t], h);
        hs[t] = fmaxf(h, 0.f);
    }
    __syncthreads();
    if (t < 2) {
        float o = bm2[t];
        for (int cc = 0; cc < 64; cc++) o = fmaf(hs[cc], M2[cc * 2 + t], o);
        out[t] = o;
    }
}

extern "C" void kernel_launch(void* const* d_in, const int* in_sizes, int n_in,
                              void* d_out, int out_size) {
    const float* X   = (const float*)d_in[0];
    const int*   A   = (const int*)d_in[1];
    const float* W1  = (const float*)d_in[2];
    const float* a1  = (const float*)d_in[3];
    const float* W21 = (const float*)d_in[4];
    const float* b21 = (const float*)d_in[5];
    const float* Wg2 = (const float*)d_in[6];
    const float* a2  = (const float*)d_in[7];
    const float* W22 = (const float*)d_in[8];
    const float* b22 = (const float*)d_in[9];
    const float* M1  = (const float*)d_in[10];
    const float* bm1 = (const float*)d_in[11];
    const float* M2  = (const float*)d_in[12];
    const float* bm2 = (const float*)d_in[13];
    float* out = (float*)d_out;

    const int smem1 = 3 * 72 * 72 * (int)sizeof(unsigned);   // 62208 B
    const int smem2 = 3 * 40 * 72 * (int)sizeof(unsigned);   // 34560 B
    static bool attr_done = false;
    if (!attr_done) {
        cudaFuncSetAttribute(k_attn<1>, cudaFuncAttributeMaxDynamicSharedMemorySize, smem1);
        cudaFuncSetAttribute(k_attn<2>, cudaFuncAttributeMaxDynamicSharedMemorySize, smem2);
        attr_done = true;
    }

    k_packh1<<<2176, 256>>>(A, X, W1, a1);   // h1+P1 blocks first, pack overlapped
    k_attn<1><<<dim3(32, KSPLIT), 256, smem1>>>();
    k_fin1<<<512, 256>>>(W21, b21, Wg2, a2);
    k_attn<2><<<dim3(32, KSPLIT), 256, smem2>>>();
    k_fin2<<<64, 256>>>(W22, b22);
    k_head<<<1, 256>>>(M1, bm1, M2, bm2, out);
}